// round 11
// baseline (speedup 1.0000x reference)
#include <cuda_runtime.h>
#include <math.h>

#define B_    1024
#define L_    50
#define D_    64
#define S_    2
#define LDX   68          // tile row stride (mult of 4 -> float4-aligned rows)
#define LDM   52          // scores / c-weight row stride (mult of 4)
#define TPB   256
#define NEGV  (-4294967295.0f)

// ---- shared memory layout (floats) ----
#define OFF_X    0                        // running x (starts as `inputs`, ends as loc)
#define OFF_T1   (OFF_X  + L_*LDX)        // temp tile 1
#define OFF_T2   (OFF_T1 + L_*LDX)        // temp tile 2
#define OFF_SC   (OFF_T2 + L_*LDX)        // 50x52 scores / c1 / c2 / epilogue scratch
#define OFF_PM   (OFF_SC + L_*LDM)        // padding mask (50)
#define OFF_G1   (OFF_PM + 64)            // ie . gw[0:64] per position
#define OFF_GLO  (OFF_G1 + 64)            // glo vector (64)
#define OFF_GW   (OFF_GLO + 64)           // gated_weight (192) + gglo scalar @192
#define SMEM_F   (OFF_GW + 200)
#define SMEM_BYTES (SMEM_F * 4)           // 52768 B -> 4 CTAs/SM

__device__ __forceinline__ float warp_sum(float v) {
#pragma unroll
    for (int o = 16; o; o >>= 1) v += __shfl_xor_sync(0xffffffffu, v, o);
    return v;
}
__device__ __forceinline__ float warp_max(float v) {
#pragma unroll
    for (int o = 16; o; o >>= 1) v = fmaxf(v, __shfl_xor_sync(0xffffffffu, v, o));
    return v;
}
__device__ __forceinline__ float sigmoidf_(float x) {
    return 1.0f / (1.0f + expf(-x));
}

// LayerNorm over D=64 for each of L_ rows (warp per row), in place.
__device__ __forceinline__ void ln_rows(float* p) {
    const int lane = threadIdx.x & 31, wid = threadIdx.x >> 5;
    for (int l = wid; l < L_; l += 8) {
        float v0 = p[l*LDX + lane], v1 = p[l*LDX + lane + 32];
        float mean = warp_sum(v0 + v1) * (1.0f/64.0f);
        float d0 = v0 - mean, d1 = v1 - mean;
        float var = warp_sum(d0*d0 + d1*d1) * (1.0f/64.0f);
        float inv = rsqrtf(var + 1e-8f);
        p[l*LDX + lane]      = d0 * inv;
        p[l*LDX + lane + 32] = d1 * inv;
    }
}

// dst[l, d] = sum_k src[l, k] * W[k, d]
// src: L_ x LDX smem; W: 64x64 GLOBAL (L1/L2-resident, broadcast across warp).
// Rows: group g owns {g, g+16, g+32}; rows 48/49 done by g<2 (warp-uniform tail).
__device__ __forceinline__ void mm_LW(float* __restrict__ dst,
                                      const float* __restrict__ src,
                                      const float* __restrict__ Wg) {
    const int tid = threadIdx.x;
    const int d4 = (tid & 15) * 4;
    const int g  = tid >> 4;
    const int rb0 = g*LDX, rb1 = (g+16)*LDX, rb2 = (g+32)*LDX;
    float a0[4] = {}, a1[4] = {}, a2[4] = {};
#pragma unroll
    for (int k = 0; k < D_; k += 4) {
        const float4 x0 = *(const float4*)&src[rb0 + k];
        const float4 x1 = *(const float4*)&src[rb1 + k];
        const float4 x2 = *(const float4*)&src[rb2 + k];
#pragma unroll
        for (int kk = 0; kk < 4; ++kk) {
            const float4 w = __ldg((const float4*)&Wg[(k + kk)*D_ + d4]);
            const float s0 = ((const float*)&x0)[kk];
            const float s1 = ((const float*)&x1)[kk];
            const float s2 = ((const float*)&x2)[kk];
            a0[0] = fmaf(s0, w.x, a0[0]); a0[1] = fmaf(s0, w.y, a0[1]);
            a0[2] = fmaf(s0, w.z, a0[2]); a0[3] = fmaf(s0, w.w, a0[3]);
            a1[0] = fmaf(s1, w.x, a1[0]); a1[1] = fmaf(s1, w.y, a1[1]);
            a1[2] = fmaf(s1, w.z, a1[2]); a1[3] = fmaf(s1, w.w, a1[3]);
            a2[0] = fmaf(s2, w.x, a2[0]); a2[1] = fmaf(s2, w.y, a2[1]);
            a2[2] = fmaf(s2, w.z, a2[2]); a2[3] = fmaf(s2, w.w, a2[3]);
        }
    }
    *(float4*)&dst[rb0 + d4] = make_float4(a0[0], a0[1], a0[2], a0[3]);
    *(float4*)&dst[rb1 + d4] = make_float4(a1[0], a1[1], a1[2], a1[3]);
    *(float4*)&dst[rb2 + d4] = make_float4(a2[0], a2[1], a2[2], a2[3]);
    if (g < 2) {                         // warp-uniform (warp 0 only)
        const int rb3 = (48 + g) * LDX;
        float b[4] = {};
#pragma unroll
        for (int k = 0; k < D_; k += 4) {
            const float4 x3 = *(const float4*)&src[rb3 + k];
#pragma unroll
            for (int kk = 0; kk < 4; ++kk) {
                const float4 w = __ldg((const float4*)&Wg[(k + kk)*D_ + d4]);
                const float s = ((const float*)&x3)[kk];
                b[0] = fmaf(s, w.x, b[0]); b[1] = fmaf(s, w.y, b[1]);
                b[2] = fmaf(s, w.z, b[2]); b[3] = fmaf(s, w.w, b[3]);
            }
        }
        *(float4*)&dst[rb3 + d4] = make_float4(b[0], b[1], b[2], b[3]);
    }
}

// apply score epilogue for one (q, kk) value
__device__ __forceinline__ float sc_fix(float v, int q, int kk, const float* pm) {
    v *= 0.125f;
    if (kk > q) v = NEGV;
    if (pm[kk] == 0.0f) v = NEGV;
    return v * pm[q];
}

// scores[q, k] = (Q[q,:] . K[k,:]) / 8, then tril/keymask NEG fill, then * pm[q]
// q rows: {g, g+16, g+32} + tail 48+g for g<2. k cols: kd + 16c (clamped, in-lane).
__device__ __forceinline__ void mm_scores(float* __restrict__ sc,
                                          const float* __restrict__ Q,
                                          const float* __restrict__ Kx,
                                          const float* __restrict__ pm) {
    const int tid = threadIdx.x;
    const int kd = tid & 15;
    const int g  = tid >> 4;
    const int q0 = g, q1 = g + 16, q2 = g + 32;
    int kb[4];
#pragma unroll
    for (int c = 0; c < 4; ++c) {
        int kk = kd + c*16; if (kk >= L_) kk = L_ - 1;
        kb[c] = kk * LDX;
    }
    float a0[4] = {}, a1[4] = {}, a2[4] = {};
#pragma unroll
    for (int d = 0; d < D_; d += 4) {
        const float4 v0 = *(const float4*)&Q[q0*LDX + d];
        const float4 v1 = *(const float4*)&Q[q1*LDX + d];
        const float4 v2 = *(const float4*)&Q[q2*LDX + d];
        float4 kv[4];
#pragma unroll
        for (int c = 0; c < 4; ++c) kv[c] = *(const float4*)&Kx[kb[c] + d];
#pragma unroll
        for (int c = 0; c < 4; ++c) {
            float t0, t1, t2;
            t0 = fmaf(v0.x, kv[c].x, a0[c]); t0 = fmaf(v0.y, kv[c].y, t0);
            t0 = fmaf(v0.z, kv[c].z, t0);    a0[c] = fmaf(v0.w, kv[c].w, t0);
            t1 = fmaf(v1.x, kv[c].x, a1[c]); t1 = fmaf(v1.y, kv[c].y, t1);
            t1 = fmaf(v1.z, kv[c].z, t1);    a1[c] = fmaf(v1.w, kv[c].w, t1);
            t2 = fmaf(v2.x, kv[c].x, a2[c]); t2 = fmaf(v2.y, kv[c].y, t2);
            t2 = fmaf(v2.z, kv[c].z, t2);    a2[c] = fmaf(v2.w, kv[c].w, t2);
        }
    }
#pragma unroll
    for (int c = 0; c < 4; ++c) {
        const int kk = kd + c*16;
        if (kk < L_) {
            sc[q0*LDM + kk] = sc_fix(a0[c], q0, kk, pm);
            sc[q1*LDM + kk] = sc_fix(a1[c], q1, kk, pm);
            sc[q2*LDM + kk] = sc_fix(a2[c], q2, kk, pm);
        }
    }
    if (g < 2) {
        const int q3 = 48 + g;
        float b[4] = {};
#pragma unroll
        for (int d = 0; d < D_; d += 4) {
            const float4 v3 = *(const float4*)&Q[q3*LDX + d];
#pragma unroll
            for (int c = 0; c < 4; ++c) {
                const float4 kv = *(const float4*)&Kx[kb[c] + d];
                float t;
                t = fmaf(v3.x, kv.x, b[c]); t = fmaf(v3.y, kv.y, t);
                t = fmaf(v3.z, kv.z, t);    b[c] = fmaf(v3.w, kv.w, t);
            }
        }
#pragma unroll
        for (int c = 0; c < 4; ++c) {
            const int kk = kd + c*16;
            if (kk < L_) sc[q3*LDM + kk] = sc_fix(b[c], q3, kk, pm);
        }
    }
}

// dst[i, d] = sum_j M[i, j] * src[j, d]  (+bias[i]) (+res[i,d]) (relu) (*pm[i])
// M: 50 x LDM smem, src/res/dst: L_ x LDX smem. i rows: {g,g+16,g+32} + tail.
template<bool RELU>
__device__ __forceinline__ void mm_SM(float* __restrict__ dst,
                                      const float* __restrict__ M,
                                      const float* __restrict__ src,
                                      const float* __restrict__ res,
                                      const float* __restrict__ bias_g,
                                      const float* __restrict__ pm) {
    const int tid = threadIdx.x;
    const int d4 = (tid & 15) * 4;
    const int g  = tid >> 4;
    const int i0 = g, i1 = g + 16, i2 = g + 32;
    float a0[4] = {}, a1[4] = {}, a2[4] = {};
#pragma unroll
    for (int j = 0; j < 48; j += 4) {
        const float4 m0 = *(const float4*)&M[i0*LDM + j];
        const float4 m1 = *(const float4*)&M[i1*LDM + j];
        const float4 m2 = *(const float4*)&M[i2*LDM + j];
#pragma unroll
        for (int jj = 0; jj < 4; ++jj) {
            const float4 sv = *(const float4*)&src[(j + jj)*LDX + d4];
            const float f0 = ((const float*)&m0)[jj];
            const float f1 = ((const float*)&m1)[jj];
            const float f2 = ((const float*)&m2)[jj];
            a0[0] = fmaf(f0, sv.x, a0[0]); a0[1] = fmaf(f0, sv.y, a0[1]);
            a0[2] = fmaf(f0, sv.z, a0[2]); a0[3] = fmaf(f0, sv.w, a0[3]);
            a1[0] = fmaf(f1, sv.x, a1[0]); a1[1] = fmaf(f1, sv.y, a1[1]);
            a1[2] = fmaf(f1, sv.z, a1[2]); a1[3] = fmaf(f1, sv.w, a1[3]);
            a2[0] = fmaf(f2, sv.x, a2[0]); a2[1] = fmaf(f2, sv.y, a2[1]);
            a2[2] = fmaf(f2, sv.z, a2[2]); a2[3] = fmaf(f2, sv.w, a2[3]);
        }
    }
#pragma unroll
    for (int j = 48; j < L_; ++j) {
        const float4 sv = *(const float4*)&src[j*LDX + d4];
        const float f0 = M[i0*LDM + j];
        const float f1 = M[i1*LDM + j];
        const float f2 = M[i2*LDM + j];
        a0[0] = fmaf(f0, sv.x, a0[0]); a0[1] = fmaf(f0, sv.y, a0[1]);
        a0[2] = fmaf(f0, sv.z, a0[2]); a0[3] = fmaf(f0, sv.w, a0[3]);
        a1[0] = fmaf(f1, sv.x, a1[0]); a1[1] = fmaf(f1, sv.y, a1[1]);
        a1[2] = fmaf(f1, sv.z, a1[2]); a1[3] = fmaf(f1, sv.w, a1[3]);
        a2[0] = fmaf(f2, sv.x, a2[0]); a2[1] = fmaf(f2, sv.y, a2[1]);
        a2[2] = fmaf(f2, sv.z, a2[2]); a2[3] = fmaf(f2, sv.w, a2[3]);
    }
    // epilogue for the 3 main rows
    {
        const int   ii[3] = {i0, i1, i2};
        const float* acc[3] = {a0, a1, a2};
#pragma unroll
        for (int r = 0; r < 3; ++r) {
            const int i = ii[r];
            const float bias = bias_g ? bias_g[i] : 0.0f;
            const float p    = pm ? pm[i] : 1.0f;
            float4 o; float* ov = (float*)&o;
            if (res) {
                const float4 rv = *(const float4*)&res[i*LDX + d4];
                const float* rp = (const float*)&rv;
#pragma unroll
                for (int c = 0; c < 4; ++c) {
                    float v = acc[r][c] + bias + rp[c];
                    if (RELU) v = fmaxf(v, 0.0f);
                    ov[c] = v * p;
                }
            } else {
#pragma unroll
                for (int c = 0; c < 4; ++c) {
                    float v = acc[r][c] + bias;
                    if (RELU) v = fmaxf(v, 0.0f);
                    ov[c] = v * p;
                }
            }
            *(float4*)&dst[i*LDX + d4] = o;
        }
    }
    if (g < 2) {
        const int i3 = 48 + g;
        float b[4] = {};
#pragma unroll
        for (int j = 0; j < 48; j += 4) {
            const float4 m3 = *(const float4*)&M[i3*LDM + j];
#pragma unroll
            for (int jj = 0; jj < 4; ++jj) {
                const float4 sv = *(const float4*)&src[(j + jj)*LDX + d4];
                const float f = ((const float*)&m3)[jj];
                b[0] = fmaf(f, sv.x, b[0]); b[1] = fmaf(f, sv.y, b[1]);
                b[2] = fmaf(f, sv.z, b[2]); b[3] = fmaf(f, sv.w, b[3]);
            }
        }
#pragma unroll
        for (int j = 48; j < L_; ++j) {
            const float4 sv = *(const float4*)&src[j*LDX + d4];
            const float f = M[i3*LDM + j];
            b[0] = fmaf(f, sv.x, b[0]); b[1] = fmaf(f, sv.y, b[1]);
            b[2] = fmaf(f, sv.z, b[2]); b[3] = fmaf(f, sv.w, b[3]);
        }
        const float bias = bias_g ? bias_g[i3] : 0.0f;
        const float p    = pm ? pm[i3] : 1.0f;
        float4 o; float* ov = (float*)&o;
        if (res) {
            const float4 rv = *(const float4*)&res[i3*LDX + d4];
            const float* rp = (const float*)&rv;
#pragma unroll
            for (int c = 0; c < 4; ++c) {
                float v = b[c] + bias + rp[c];
                if (RELU) v = fmaxf(v, 0.0f);
                ov[c] = v * p;
            }
        } else {
#pragma unroll
            for (int c = 0; c < 4; ++c) {
                float v = b[c] + bias;
                if (RELU) v = fmaxf(v, 0.0f);
                ov[c] = v * p;
            }
        }
        *(float4*)&dst[i3*LDX + d4] = o;
    }
}

// gather + positional embedding + mask into dst (L_ x LDX), no LN.
__device__ __forceinline__ void build_inputs(float* __restrict__ dst,
                                             const int* __restrict__ ui_row,
                                             const float* __restrict__ item_emb,
                                             const float* __restrict__ pos_emb,
                                             const float* __restrict__ pm) {
    const int tid = threadIdx.x;
    for (int idx = tid; idx < L_*16; idx += TPB) {
        const int l = idx >> 4, c4 = (idx & 15) * 4;
        const int it = __ldg(&ui_row[l]);
        const float4 e  = __ldg((const float4*)&item_emb[it*D_ + c4]);
        const float4 pe = __ldg((const float4*)&pos_emb[l*D_ + c4]);
        const float p = pm[l];
        *(float4*)&dst[l*LDX + c4] =
            make_float4((e.x+pe.x)*p, (e.y+pe.y)*p, (e.z+pe.z)*p, (e.w+pe.w)*p);
    }
}

__global__ void __launch_bounds__(TPB, 4)
fissa_kernel(const int* __restrict__ ui, const int* __restrict__ pi,
             const int* __restrict__ ni, const float* __restrict__ pmask,
             const float* __restrict__ item_emb, const float* __restrict__ pos_emb,
             const float* __restrict__ Qs, const float* __restrict__ Ks,
             const float* __restrict__ Vs,
             const float* __restrict__ c1w, const float* __restrict__ c1b,
             const float* __restrict__ c2w, const float* __restrict__ c2b,
             const float* __restrict__ qitem,
             const float* __restrict__ Klba, const float* __restrict__ Vlba,
             const float* __restrict__ l1w, const float* __restrict__ l1b,
             const float* __restrict__ l2w, const float* __restrict__ l2b,
             const float* __restrict__ gw, const float* __restrict__ gb,
             float* __restrict__ out) {
    extern __shared__ float sm[];
    float* s_x   = sm + OFF_X;
    float* t1    = sm + OFF_T1;
    float* t2    = sm + OFF_T2;
    float* s_sc  = sm + OFF_SC;
    float* s_pm  = sm + OFF_PM;
    float* s_g1  = sm + OFF_G1;
    float* s_glo = sm + OFF_GLO;
    float* s_gw  = sm + OFF_GW;

    const int b    = blockIdx.x;
    const int tid  = threadIdx.x;
    const int lane = tid & 31;
    const int wid  = tid >> 5;

    // ---- prologue ----
    if (tid < 192) s_gw[tid] = gw[tid];
    if (tid < L_)  s_pm[tid] = pmask[b*L_ + tid];
    __syncthreads();

    build_inputs(s_x, ui + b*L_, item_emb, pos_emb, s_pm);
    // g1[l] = ie[l] . gw[0:64]
    for (int l = wid; l < L_; l += 8) {
        const int it = __ldg(&ui[b*L_ + l]);
        float v = item_emb[it*D_ + lane] * s_gw[lane]
                + item_emb[it*D_ + lane + 32] * s_gw[lane + 32];
        v = warp_sum(v);
        if (lane == 0) s_g1[l] = v;
    }
    __syncthreads();
    ln_rows(s_x);                        // x = inputs = LN((ie + pos) * pm)
    __syncthreads();

    // ---- S self-attention blocks ----
    for (int s = 0; s < S_; ++s) {
        mm_LW(t1, s_x, Qs + s*D_*D_);            // Qx
        mm_LW(t2, s_x, Ks + s*D_*D_);            // Kx
        __syncthreads();
        mm_scores(s_sc, t1, t2, s_pm);
        __syncthreads();
        mm_LW(t1, s_x, Vs + s*D_*D_);            // Vx (Qx dead)
        __syncthreads();
        mm_SM<false>(t2, s_sc, t1, s_x, nullptr, nullptr);   // att = sc@Vx + x
        __syncthreads();
        // stage c1 (scores dead) + LN(att)
        for (int idx = tid; idx < L_*L_; idx += TPB) {
            const int i = idx / L_, j = idx - i*L_;
            s_sc[i*LDM + j] = __ldg(&c1w[s*L_*L_ + idx]);
        }
        ln_rows(t2);
        __syncthreads();
        mm_SM<true>(t1, s_sc, t2, nullptr, c1b + s*L_, nullptr);  // h
        __syncthreads();
        for (int idx = tid; idx < L_*L_; idx += TPB) {
            const int i = idx / L_, j = idx - i*L_;
            s_sc[i*LDM + j] = __ldg(&c2w[s*L_*L_ + idx]);
        }
        __syncthreads();
        mm_SM<false>(s_x, s_sc, t1, t2, c2b + s*L_, s_pm);   // ff -> x
        __syncthreads();
        ln_rows(s_x);
        __syncthreads();
    }
    // s_x = loc from here on (untouched below)

    // ---- LBA global attention (tile-free formulation) ----
    build_inputs(t1, ui + b*L_, item_emb, pos_emb, s_pm);
    __syncthreads();
    ln_rows(t1);
    __syncthreads();

    float* kq = s_sc;          // 64
    float* lg = s_sc + 64;     // 50 logits -> softmax probs
    float* wv = s_sc + 128;    // 64 column sums

    // kq[e] = Klba[e,:] . q
    for (int e = wid; e < D_; e += 8) {
        float v = __ldg(&Klba[e*D_ + lane]) * __ldg(&qitem[lane])
                + __ldg(&Klba[e*D_ + lane + 32]) * __ldg(&qitem[lane + 32]);
        v = warp_sum(v);
        if (lane == 0) kq[e] = v;
    }
    __syncthreads();
    // lg[l] = inputs[l] . kq  (+ key mask)
    for (int l = wid; l < L_; l += 8) {
        float v = t1[l*LDX + lane] * kq[lane]
                + t1[l*LDX + lane + 32] * kq[lane + 32];
        v = warp_sum(v);
        if (lane == 0) lg[l] = (s_pm[l] == 0.0f) ? NEGV : v;
    }
    __syncthreads();
    // softmax over 50 (warp 0)
    if (wid == 0) {
        float v0 = (lane < L_) ? lg[lane] : -3.0e38f;
        float v1 = (lane + 32 < L_) ? lg[lane + 32] : -3.0e38f;
        float m = warp_max(fmaxf(v0, v1));
        float e0 = (lane < L_) ? expf(v0 - m) : 0.0f;
        float e1 = (lane + 32 < L_) ? expf(v1 - m) : 0.0f;
        float ssum = warp_sum(e0 + e1);
        if (lane < L_)      lg[lane]      = e0 / ssum;
        if (lane + 32 < L_) lg[lane + 32] = e1 / ssum;
    }
    __syncthreads();
    // wv[e] = sum_l p[l] * inputs[l, e]
    if (tid < D_) {
        float a = 0.0f;
        for (int l = 0; l < L_; ++l) a = fmaf(lg[l], t1[l*LDX + tid], a);
        wv[tid] = a;
    }
    __syncthreads();
    // glo[d] = sum_e wv[e] * Vlba[e, d]
    if (tid < D_) {
        float a = 0.0f;
        for (int e = 0; e < D_; ++e) a = fmaf(wv[e], __ldg(&Vlba[e*D_ + tid]), a);
        s_glo[tid] = a;
    }
    __syncthreads();
    // LN -> l1/l2 residual -> LN -> gglo scalar (warp 0)
    if (wid == 0) {
        float v0 = s_glo[lane], v1 = s_glo[lane + 32];
        float mean = warp_sum(v0 + v1) * (1.0f/64.0f);
        float d0 = v0 - mean, d1 = v1 - mean;
        float var = warp_sum(d0*d0 + d1*d1) * (1.0f/64.0f);
        float inv = rsqrtf(var + 1e-8f);
        float g0 = d0 * inv, g1v = d1 * inv;
        const float w1 = l1w[0], bb1 = l1b[0], w2 = l2w[0], bb2 = l2b[0];
        float h0 = fmaxf(w1*g0 + bb1, 0.0f);
        float h1 = fmaxf(w1*g1v + bb1, 0.0f);
        g0  = w2*h0 + bb2 + g0;
        g1v = w2*h1 + bb2 + g1v;
        mean = warp_sum(g0 + g1v) * (1.0f/64.0f);
        d0 = g0 - mean; d1 = g1v - mean;
        var = warp_sum(d0*d0 + d1*d1) * (1.0f/64.0f);
        inv = rsqrtf(var + 1e-8f);
        g0 = d0 * inv; g1v = d1 * inv;
        s_glo[lane] = g0; s_glo[lane + 32] = g1v;
        float gg = warp_sum(g0 * s_gw[64 + lane] + g1v * s_gw[96 + lane]);
        if (lane == 0) s_gw[192] = gg;   // glo . gw[64:128]
    }
    __syncthreads();

    // ---- gated fusion + final LN + pos/neg dots ----
    const float gbias = gb[0];
    for (int t = wid; t < 2*L_; t += 8) {
        const int pn = (t >= L_);
        const int l  = t - pn*L_;
        const int*  items = pn ? ni : pi;
        const int   it = __ldg(&items[b*L_ + l]);
        const float e0 = item_emb[it*D_ + lane];
        const float e1 = item_emb[it*D_ + lane + 32];
        const float dot3 = warp_sum(e0 * s_gw[128 + lane] + e1 * s_gw[160 + lane]);
        const float logit = s_g1[l] + s_gw[192] + dot3 + gbias;
        const float g = sigmoidf_(sigmoidf_(logit));
        float o0 = (s_x[l*LDX + lane]      * g + s_glo[lane]      * (1.0f - g)) * s_pm[l];
        float o1 = (s_x[l*LDX + lane + 32] * g + s_glo[lane + 32] * (1.0f - g)) * s_pm[l];
        const float mean = warp_sum(o0 + o1) * (1.0f/64.0f);
        const float d0 = o0 - mean, d1 = o1 - mean;
        const float var = warp_sum(d0*d0 + d1*d1) * (1.0f/64.0f);
        const float inv = rsqrtf(var + 1e-8f);
        const float r = warp_sum(d0*inv*e0 + d1*inv*e1);
        if (lane == 0) out[pn*B_*L_ + b*L_ + l] = r;
    }
}

extern "C" void kernel_launch(void* const* d_in, const int* in_sizes, int n_in,
                              void* d_out, int out_size) {
    const int*   ui       = (const int*)  d_in[0];
    const int*   pi       = (const int*)  d_in[1];
    const int*   ni       = (const int*)  d_in[2];
    const float* pmask    = (const float*)d_in[3];
    const float* item_emb = (const float*)d_in[4];
    const float* pos_emb  = (const float*)d_in[5];
    const float* Qs       = (const float*)d_in[6];
    const float* Ks       = (const float*)d_in[7];
    const float* Vs       = (const float*)d_in[8];
    const float* c1w      = (const float*)d_in[9];
    const float* c1b      = (const float*)d_in[10];
    const float* c2w      = (const float*)d_in[11];
    const float* c2b      = (const float*)d_in[12];
    const float* qitem    = (const float*)d_in[13];
    const float* Klba     = (const float*)d_in[14];
    const float* Vlba     = (const float*)d_in[15];
    const float* l1w      = (const float*)d_in[16];
    const float* l1b      = (const float*)d_in[17];
    const float* l2w      = (const float*)d_in[18];
    const float* l2b      = (const float*)d_in[19];
    const float* gw       = (const float*)d_in[20];
    const float* gb       = (const float*)d_in[21];
    float* out = (float*)d_out;

    cudaFuncSetAttribute(fissa_kernel,
                         cudaFuncAttributeMaxDynamicSharedMemorySize, SMEM_BYTES);
    fissa_kernel<<<B_, TPB, SMEM_BYTES>>>(ui, pi, ni, pmask, item_emb, pos_emb,
                                          Qs, Ks, Vs, c1w, c1b, c2w, c2b, qitem,
                                          Klba, Vlba, l1w, l1b, l2w, l2b, gw, gb,
                                          out);
}

// round 13
// speedup vs baseline: 1.0106x; 1.0106x over previous
#include <cuda_runtime.h>
#include <math.h>

#define B_    1024
#define L_    50
#define D_    64
#define S_    2
#define LDX   68          // tile row stride (mult of 4 -> float4-aligned rows)
#define LDM   52          // scores / c-weight row stride (mult of 4)
#define TPB   256
#define NEGV  (-4294967295.0f)

// ---- shared memory layout (floats) ----
#define OFF_X    0                        // running x (starts as `inputs`, ends as loc)
#define OFF_T1   (OFF_X  + L_*LDX)        // temp tile 1
#define OFF_T2   (OFF_T1 + L_*LDX)        // temp tile 2
#define OFF_SC   (OFF_T2 + L_*LDX)        // 50x52 scores / c1 / c2 / epilogue scratch
#define OFF_PM   (OFF_SC + L_*LDM)        // padding mask (50)
#define OFF_G1   (OFF_PM + 64)            // ie . gw[0:64] per position
#define OFF_GLO  (OFF_G1 + 64)            // glo vector (64)
#define OFF_GW   (OFF_GLO + 64)           // gated_weight (192) + gglo scalar @192
#define SMEM_F   (OFF_GW + 200)
#define SMEM_BYTES (SMEM_F * 4)           // 52768 B -> 4 CTAs/SM

__device__ __forceinline__ float warp_sum(float v) {
#pragma unroll
    for (int o = 16; o; o >>= 1) v += __shfl_xor_sync(0xffffffffu, v, o);
    return v;
}
__device__ __forceinline__ float warp_max(float v) {
#pragma unroll
    for (int o = 16; o; o >>= 1) v = fmaxf(v, __shfl_xor_sync(0xffffffffu, v, o));
    return v;
}
__device__ __forceinline__ float sigmoidf_(float x) {
    return 1.0f / (1.0f + expf(-x));
}

// acc += s * vec (componentwise), all in registers
__device__ __forceinline__ void fma4(float4& acc, float s, const float4 vec) {
    acc.x = fmaf(s, vec.x, acc.x);
    acc.y = fmaf(s, vec.y, acc.y);
    acc.z = fmaf(s, vec.z, acc.z);
    acc.w = fmaf(s, vec.w, acc.w);
}

// scalar acc += dot(q, k)
__device__ __forceinline__ float dot4acc(float acc, float4 q, float4 k) {
    float t = fmaf(q.x, k.x, acc);
    t = fmaf(q.y, k.y, t);
    t = fmaf(q.z, k.z, t);
    return fmaf(q.w, k.w, t);
}

// LayerNorm over D=64 for each of L_ rows (warp per row), in place.
__device__ __forceinline__ void ln_rows(float* p) {
    const int lane = threadIdx.x & 31, wid = threadIdx.x >> 5;
    for (int l = wid; l < L_; l += 8) {
        float v0 = p[l*LDX + lane], v1 = p[l*LDX + lane + 32];
        float mean = warp_sum(v0 + v1) * (1.0f/64.0f);
        float d0 = v0 - mean, d1 = v1 - mean;
        float var = warp_sum(d0*d0 + d1*d1) * (1.0f/64.0f);
        float inv = rsqrtf(var + 1e-8f);
        p[l*LDX + lane]      = d0 * inv;
        p[l*LDX + lane + 32] = d1 * inv;
    }
}

// dst[l, d] = sum_k src[l, k] * W[k, d]
// src: L_ x LDX smem; W: 64x64 GLOBAL (L1/L2-resident, broadcast across warp).
// Rows: group g owns {g, g+16, g+32}; rows 48/49 done by warp 0 (g<2) tail.
__device__ __forceinline__ void mm_LW(float* __restrict__ dst,
                                      const float* __restrict__ src,
                                      const float* __restrict__ Wg) {
    const int tid = threadIdx.x;
    const int d4 = (tid & 15) * 4;
    const int g  = tid >> 4;
    const int rb0 = g*LDX, rb1 = (g+16)*LDX, rb2 = (g+32)*LDX;
    float4 a0 = make_float4(0.f,0.f,0.f,0.f), a1 = a0, a2 = a0;
#pragma unroll
    for (int k = 0; k < D_; k += 4) {
        const float4 x0 = *(const float4*)&src[rb0 + k];
        const float4 x1 = *(const float4*)&src[rb1 + k];
        const float4 x2 = *(const float4*)&src[rb2 + k];
#pragma unroll
        for (int kk = 0; kk < 4; ++kk) {
            const float4 wv4 = __ldg((const float4*)&Wg[(k + kk)*D_ + d4]);
            const float s0 = ((const float*)&x0)[kk];
            const float s1 = ((const float*)&x1)[kk];
            const float s2 = ((const float*)&x2)[kk];
            fma4(a0, s0, wv4);
            fma4(a1, s1, wv4);
            fma4(a2, s2, wv4);
        }
    }
    *(float4*)&dst[rb0 + d4] = a0;
    *(float4*)&dst[rb1 + d4] = a1;
    *(float4*)&dst[rb2 + d4] = a2;
    if (g < 2) {                         // warp-uniform (warp 0 only)
        const int rb3 = (48 + g) * LDX;
        float4 bacc = make_float4(0.f,0.f,0.f,0.f);
#pragma unroll
        for (int k = 0; k < D_; k += 4) {
            const float4 x3 = *(const float4*)&src[rb3 + k];
#pragma unroll
            for (int kk = 0; kk < 4; ++kk) {
                const float4 wv4 = __ldg((const float4*)&Wg[(k + kk)*D_ + d4]);
                fma4(bacc, ((const float*)&x3)[kk], wv4);
            }
        }
        *(float4*)&dst[rb3 + d4] = bacc;
    }
}

// apply score epilogue for one (q, kk) value
__device__ __forceinline__ float sc_fix(float v, int q, int kk, const float* pm) {
    v *= 0.125f;
    if (kk > q) v = NEGV;
    if (pm[kk] == 0.0f) v = NEGV;
    return v * pm[q];
}

// scores[q, k] = (Q[q,:] . K[k,:]) / 8, then tril/keymask NEG fill, then * pm[q]
// q rows: {g, g+16, g+32} + tail 48+g for g<2. k cols: kd + 16c (col 3 predicated).
__device__ __forceinline__ void mm_scores(float* __restrict__ sc,
                                          const float* __restrict__ Q,
                                          const float* __restrict__ Kx,
                                          const float* __restrict__ pm) {
    const int tid = threadIdx.x;
    const int kd = tid & 15;
    const int g  = tid >> 4;
    const int q0 = g, q1 = g + 16, q2 = g + 32;
    const int k0 = kd, k1 = kd + 16, k2 = kd + 32, k3 = kd + 48;
    const int kb0 = k0*LDX, kb1 = k1*LDX, kb2 = k2*LDX;
    const int kb3 = (k3 < L_ ? k3 : L_ - 1) * LDX;
    float4 a0 = make_float4(0.f,0.f,0.f,0.f), a1 = a0, a2 = a0;
#pragma unroll
    for (int d = 0; d < D_; d += 4) {
        const float4 v0 = *(const float4*)&Q[q0*LDX + d];
        const float4 v1 = *(const float4*)&Q[q1*LDX + d];
        const float4 v2 = *(const float4*)&Q[q2*LDX + d];
        const float4 c0 = *(const float4*)&Kx[kb0 + d];
        const float4 c1 = *(const float4*)&Kx[kb1 + d];
        const float4 c2 = *(const float4*)&Kx[kb2 + d];
        const float4 c3 = *(const float4*)&Kx[kb3 + d];
        a0.x = dot4acc(a0.x, v0, c0); a0.y = dot4acc(a0.y, v0, c1);
        a0.z = dot4acc(a0.z, v0, c2); a0.w = dot4acc(a0.w, v0, c3);
        a1.x = dot4acc(a1.x, v1, c0); a1.y = dot4acc(a1.y, v1, c1);
        a1.z = dot4acc(a1.z, v1, c2); a1.w = dot4acc(a1.w, v1, c3);
        a2.x = dot4acc(a2.x, v2, c0); a2.y = dot4acc(a2.y, v2, c1);
        a2.z = dot4acc(a2.z, v2, c2); a2.w = dot4acc(a2.w, v2, c3);
    }
    sc[q0*LDM + k0] = sc_fix(a0.x, q0, k0, pm);
    sc[q0*LDM + k1] = sc_fix(a0.y, q0, k1, pm);
    sc[q0*LDM + k2] = sc_fix(a0.z, q0, k2, pm);
    sc[q1*LDM + k0] = sc_fix(a1.x, q1, k0, pm);
    sc[q1*LDM + k1] = sc_fix(a1.y, q1, k1, pm);
    sc[q1*LDM + k2] = sc_fix(a1.z, q1, k2, pm);
    sc[q2*LDM + k0] = sc_fix(a2.x, q2, k0, pm);
    sc[q2*LDM + k1] = sc_fix(a2.y, q2, k1, pm);
    sc[q2*LDM + k2] = sc_fix(a2.z, q2, k2, pm);
    if (k3 < L_) {
        sc[q0*LDM + k3] = sc_fix(a0.w, q0, k3, pm);
        sc[q1*LDM + k3] = sc_fix(a1.w, q1, k3, pm);
        sc[q2*LDM + k3] = sc_fix(a2.w, q2, k3, pm);
    }
    if (g < 2) {                         // warp-uniform tail: q = 48 + g
        const int q3 = 48 + g;
        float4 bacc = make_float4(0.f,0.f,0.f,0.f);
#pragma unroll
        for (int d = 0; d < D_; d += 4) {
            const float4 v3 = *(const float4*)&Q[q3*LDX + d];
            bacc.x = dot4acc(bacc.x, v3, *(const float4*)&Kx[kb0 + d]);
            bacc.y = dot4acc(bacc.y, v3, *(const float4*)&Kx[kb1 + d]);
            bacc.z = dot4acc(bacc.z, v3, *(const float4*)&Kx[kb2 + d]);
            bacc.w = dot4acc(bacc.w, v3, *(const float4*)&Kx[kb3 + d]);
        }
        sc[q3*LDM + k0] = sc_fix(bacc.x, q3, k0, pm);
        sc[q3*LDM + k1] = sc_fix(bacc.y, q3, k1, pm);
        sc[q3*LDM + k2] = sc_fix(bacc.z, q3, k2, pm);
        if (k3 < L_) sc[q3*LDM + k3] = sc_fix(bacc.w, q3, k3, pm);
    }
}

// dst[i, d] = sum_j M[i, j] * src[j, d]  (+bias[i]) (+res[i,d]) (relu) (*pm[i])
// M: 50 x LDM smem, src/res/dst: L_ x LDX smem. i rows: {g,g+16,g+32} + tail.
template<bool RELU>
__device__ __forceinline__ void sm_epi(float* __restrict__ dst,
                                       const float* __restrict__ res,
                                       const float* __restrict__ bias_g,
                                       const float* __restrict__ pm,
                                       float4 acc, int irow, int d4) {
    const float bias_ = bias_g ? bias_g[irow] : 0.0f;
    const float p_    = pm ? pm[irow] : 1.0f;
    float4 o_;
    if (res) {
        const float4 rv_ = *(const float4*)&res[irow*LDX + d4];
        o_.x = acc.x + bias_ + rv_.x;
        o_.y = acc.y + bias_ + rv_.y;
        o_.z = acc.z + bias_ + rv_.z;
        o_.w = acc.w + bias_ + rv_.w;
    } else {
        o_.x = acc.x + bias_; o_.y = acc.y + bias_;
        o_.z = acc.z + bias_; o_.w = acc.w + bias_;
    }
    if (RELU) {
        o_.x = fmaxf(o_.x, 0.0f); o_.y = fmaxf(o_.y, 0.0f);
        o_.z = fmaxf(o_.z, 0.0f); o_.w = fmaxf(o_.w, 0.0f);
    }
    o_.x *= p_; o_.y *= p_; o_.z *= p_; o_.w *= p_;
    *(float4*)&dst[irow*LDX + d4] = o_;
}

template<bool RELU>
__device__ __forceinline__ void mm_SM(float* __restrict__ dst,
                                      const float* __restrict__ M,
                                      const float* __restrict__ src,
                                      const float* __restrict__ res,
                                      const float* __restrict__ bias_g,
                                      const float* __restrict__ pm) {
    const int tid = threadIdx.x;
    const int d4 = (tid & 15) * 4;
    const int g  = tid >> 4;
    const int i0 = g, i1 = g + 16, i2 = g + 32;
    float4 a0 = make_float4(0.f,0.f,0.f,0.f), a1 = a0, a2 = a0;
#pragma unroll
    for (int j = 0; j < 48; j += 4) {
        const float4 m0 = *(const float4*)&M[i0*LDM + j];
        const float4 m1 = *(const float4*)&M[i1*LDM + j];
        const float4 m2 = *(const float4*)&M[i2*LDM + j];
#pragma unroll
        for (int jj = 0; jj < 4; ++jj) {
            const float4 sv = *(const float4*)&src[(j + jj)*LDX + d4];
            fma4(a0, ((const float*)&m0)[jj], sv);
            fma4(a1, ((const float*)&m1)[jj], sv);
            fma4(a2, ((const float*)&m2)[jj], sv);
        }
    }
#pragma unroll
    for (int j = 48; j < L_; ++j) {
        const float4 sv = *(const float4*)&src[j*LDX + d4];
        fma4(a0, M[i0*LDM + j], sv);
        fma4(a1, M[i1*LDM + j], sv);
        fma4(a2, M[i2*LDM + j], sv);
    }
    sm_epi<RELU>(dst, res, bias_g, pm, a0, i0, d4);
    sm_epi<RELU>(dst, res, bias_g, pm, a1, i1, d4);
    sm_epi<RELU>(dst, res, bias_g, pm, a2, i2, d4);
    if (g < 2) {                         // warp-uniform tail: i = 48 + g
        const int i3 = 48 + g;
        float4 bacc = make_float4(0.f,0.f,0.f,0.f);
#pragma unroll
        for (int j = 0; j < 48; j += 4) {
            const float4 m3 = *(const float4*)&M[i3*LDM + j];
#pragma unroll
            for (int jj = 0; jj < 4; ++jj) {
                const float4 sv = *(const float4*)&src[(j + jj)*LDX + d4];
                fma4(bacc, ((const float*)&m3)[jj], sv);
            }
        }
#pragma unroll
        for (int j = 48; j < L_; ++j) {
            const float4 sv = *(const float4*)&src[j*LDX + d4];
            fma4(bacc, M[i3*LDM + j], sv);
        }
        sm_epi<RELU>(dst, res, bias_g, pm, bacc, i3, d4);
    }
}

// gather + positional embedding + mask into dst (L_ x LDX), no LN.
__device__ __forceinline__ void build_inputs(float* __restrict__ dst,
                                             const int* __restrict__ ui_row,
                                             const float* __restrict__ item_emb,
                                             const float* __restrict__ pos_emb,
                                             const float* __restrict__ pm) {
    const int tid = threadIdx.x;
    for (int idx = tid; idx < L_*16; idx += TPB) {
        const int l = idx >> 4, c4 = (idx & 15) * 4;
        const int it = __ldg(&ui_row[l]);
        const float4 e  = __ldg((const float4*)&item_emb[it*D_ + c4]);
        const float4 pe = __ldg((const float4*)&pos_emb[l*D_ + c4]);
        const float p = pm[l];
        *(float4*)&dst[l*LDX + c4] =
            make_float4((e.x+pe.x)*p, (e.y+pe.y)*p, (e.z+pe.z)*p, (e.w+pe.w)*p);
    }
}

__global__ void __launch_bounds__(TPB, 4)
fissa_kernel(const int* __restrict__ ui, const int* __restrict__ pi,
             const int* __restrict__ ni, const float* __restrict__ pmask,
             const float* __restrict__ item_emb, const float* __restrict__ pos_emb,
             const float* __restrict__ Qs, const float* __restrict__ Ks,
             const float* __restrict__ Vs,
             const float* __restrict__ c1w, const float* __restrict__ c1b,
             const float* __restrict__ c2w, const float* __restrict__ c2b,
             const float* __restrict__ qitem,
             const float* __restrict__ Klba, const float* __restrict__ Vlba,
             const float* __restrict__ l1w, const float* __restrict__ l1b,
             const float* __restrict__ l2w, const float* __restrict__ l2b,
             const float* __restrict__ gw, const float* __restrict__ gb,
             float* __restrict__ out) {
    extern __shared__ float sm[];
    float* s_x   = sm + OFF_X;
    float* t1    = sm + OFF_T1;
    float* t2    = sm + OFF_T2;
    float* s_sc  = sm + OFF_SC;
    float* s_pm  = sm + OFF_PM;
    float* s_g1  = sm + OFF_G1;
    float* s_glo = sm + OFF_GLO;
    float* s_gw  = sm + OFF_GW;

    const int b    = blockIdx.x;
    const int tid  = threadIdx.x;
    const int lane = tid & 31;
    const int wid  = tid >> 5;

    // ---- prologue ----
    if (tid < 192) s_gw[tid] = gw[tid];
    if (tid < L_)  s_pm[tid] = pmask[b*L_ + tid];
    __syncthreads();

    build_inputs(s_x, ui + b*L_, item_emb, pos_emb, s_pm);
    // g1[l] = ie[l] . gw[0:64]
    for (int l = wid; l < L_; l += 8) {
        const int it = __ldg(&ui[b*L_ + l]);
        float v = item_emb[it*D_ + lane] * s_gw[lane]
                + item_emb[it*D_ + lane + 32] * s_gw[lane + 32];
        v = warp_sum(v);
        if (lane == 0) s_g1[l] = v;
    }
    __syncthreads();
    ln_rows(s_x);                        // x = inputs = LN((ie + pos) * pm)
    __syncthreads();

    // ---- S self-attention blocks ----
    for (int s = 0; s < S_; ++s) {
        mm_LW(t1, s_x, Qs + s*D_*D_);            // Qx
        mm_LW(t2, s_x, Ks + s*D_*D_);            // Kx
        __syncthreads();
        mm_scores(s_sc, t1, t2, s_pm);
        __syncthreads();
        mm_LW(t1, s_x, Vs + s*D_*D_);            // Vx (Qx dead)
        __syncthreads();
        mm_SM<false>(t2, s_sc, t1, s_x, nullptr, nullptr);   // att = sc@Vx + x
        __syncthreads();
        // stage c1 (scores dead) + LN(att)
        for (int idx = tid; idx < L_*L_; idx += TPB) {
            const int i = idx / L_, j = idx - i*L_;
            s_sc[i*LDM + j] = __ldg(&c1w[s*L_*L_ + idx]);
        }
        ln_rows(t2);
        __syncthreads();
        mm_SM<true>(t1, s_sc, t2, nullptr, c1b + s*L_, nullptr);  // h
        __syncthreads();
        for (int idx = tid; idx < L_*L_; idx += TPB) {
            const int i = idx / L_, j = idx - i*L_;
            s_sc[i*LDM + j] = __ldg(&c2w[s*L_*L_ + idx]);
        }
        __syncthreads();
        mm_SM<false>(s_x, s_sc, t1, t2, c2b + s*L_, s_pm);   // ff -> x
        __syncthreads();
        ln_rows(s_x);
        __syncthreads();
    }
    // s_x = loc from here on (untouched below)

    // ---- LBA global attention (tile-free formulation) ----
    build_inputs(t1, ui + b*L_, item_emb, pos_emb, s_pm);
    __syncthreads();
    ln_rows(t1);
    __syncthreads();

    float* kq = s_sc;          // 64
    float* lg = s_sc + 64;     // 50 logits -> softmax probs
    float* wv = s_sc + 128;    // 64 column sums

    // kq[e] = Klba[e,:] . q
    for (int e = wid; e < D_; e += 8) {
        float v = __ldg(&Klba[e*D_ + lane]) * __ldg(&qitem[lane])
                + __ldg(&Klba[e*D_ + lane + 32]) * __ldg(&qitem[lane + 32]);
        v = warp_sum(v);
        if (lane == 0) kq[e] = v;
    }
    __syncthreads();
    // lg[l] = inputs[l] . kq  (+ key mask)
    for (int l = wid; l < L_; l += 8) {
        float v = t1[l*LDX + lane] * kq[lane]
                + t1[l*LDX + lane + 32] * kq[lane + 32];
        v = warp_sum(v);
        if (lane == 0) lg[l] = (s_pm[l] == 0.0f) ? NEGV : v;
    }
    __syncthreads();
    // softmax over 50 (warp 0)
    if (wid == 0) {
        float v0 = (lane < L_) ? lg[lane] : -3.0e38f;
        float v1 = (lane + 32 < L_) ? lg[lane + 32] : -3.0e38f;
        float m = warp_max(fmaxf(v0, v1));
        float e0 = (lane < L_) ? expf(v0 - m) : 0.0f;
        float e1 = (lane + 32 < L_) ? expf(v1 - m) : 0.0f;
        float ssum = warp_sum(e0 + e1);
        if (lane < L_)      lg[lane]      = e0 / ssum;
        if (lane + 32 < L_) lg[lane + 32] = e1 / ssum;
    }
    __syncthreads();
    // wv[e] = sum_l p[l] * inputs[l, e]
    if (tid < D_) {
        float a = 0.0f;
        for (int l = 0; l < L_; ++l) a = fmaf(lg[l], t1[l*LDX + tid], a);
        wv[tid] = a;
    }
    __syncthreads();
    // glo[d] = sum_e wv[e] * Vlba[e, d]
    if (tid < D_) {
        float a = 0.0f;
        for (int e = 0; e < D_; ++e) a = fmaf(wv[e], __ldg(&Vlba[e*D_ + tid]), a);
        s_glo[tid] = a;
    }
    __syncthreads();
    // LN -> l1/l2 residual -> LN -> gglo scalar (warp 0)
    if (wid == 0) {
        float v0 = s_glo[lane], v1 = s_glo[lane + 32];
        float mean = warp_sum(v0 + v1) * (1.0f/64.0f);
        float d0 = v0 - mean, d1 = v1 - mean;
        float var = warp_sum(d0*d0 + d1*d1) * (1.0f/64.0f);
        float inv = rsqrtf(var + 1e-8f);
        float g0 = d0 * inv, g1v = d1 * inv;
        const float w1 = l1w[0], bb1 = l1b[0], w2 = l2w[0], bb2 = l2b[0];
        float h0 = fmaxf(w1*g0 + bb1, 0.0f);
        float h1 = fmaxf(w1*g1v + bb1, 0.0f);
        g0  = w2*h0 + bb2 + g0;
        g1v = w2*h1 + bb2 + g1v;
        mean = warp_sum(g0 + g1v) * (1.0f/64.0f);
        d0 = g0 - mean; d1 = g1v - mean;
        var = warp_sum(d0*d0 + d1*d1) * (1.0f/64.0f);
        inv = rsqrtf(var + 1e-8f);
        g0 = d0 * inv; g1v = d1 * inv;
        s_glo[lane] = g0; s_glo[lane + 32] = g1v;
        float gg = warp_sum(g0 * s_gw[64 + lane] + g1v * s_gw[96 + lane]);
        if (lane == 0) s_gw[192] = gg;   // glo . gw[64:128]
    }
    __syncthreads();

    // ---- gated fusion + final LN + pos/neg dots ----
    const float gbias = gb[0];
    for (int t = wid; t < 2*L_; t += 8) {
        const int pn = (t >= L_);
        const int l  = t - pn*L_;
        const int*  items = pn ? ni : pi;
        const int   it = __ldg(&items[b*L_ + l]);
        const float e0 = item_emb[it*D_ + lane];
        const float e1 = item_emb[it*D_ + lane + 32];
        const float dot3 = warp_sum(e0 * s_gw[128 + lane] + e1 * s_gw[160 + lane]);
        const float logit = s_g1[l] + s_gw[192] + dot3 + gbias;
        const float g = sigmoidf_(sigmoidf_(logit));
        float o0 = (s_x[l*LDX + lane]      * g + s_glo[lane]      * (1.0f - g)) * s_pm[l];
        float o1 = (s_x[l*LDX + lane + 32] * g + s_glo[lane + 32] * (1.0f - g)) * s_pm[l];
        const float mean = warp_sum(o0 + o1) * (1.0f/64.0f);
        const float d0 = o0 - mean, d1 = o1 - mean;
        const float var = warp_sum(d0*d0 + d1*d1) * (1.0f/64.0f);
        const float inv = rsqrtf(var + 1e-8f);
        const float r = warp_sum(d0*inv*e0 + d1*inv*e1);
        if (lane == 0) out[pn*B_*L_ + b*L_ + l] = r;
    }
}

extern "C" void kernel_launch(void* const* d_in, const int* in_sizes, int n_in,
                              void* d_out, int out_size) {
    const int*   ui       = (const int*)  d_in[0];
    const int*   pi       = (const int*)  d_in[1];
    const int*   ni       = (const int*)  d_in[2];
    const float* pmask    = (const float*)d_in[3];
    const float* item_emb = (const float*)d_in[4];
    const float* pos_emb  = (const float*)d_in[5];
    const float* Qs       = (const float*)d_in[6];
    const float* Ks       = (const float*)d_in[7];
    const float* Vs       = (const float*)d_in[8];
    const float* c1w      = (const float*)d_in[9];
    const float* c1b      = (const float*)d_in[10];
    const float* c2w      = (const float*)d_in[11];
    const float* c2b      = (const float*)d_in[12];
    const float* qitem    = (const float*)d_in[13];
    const float* Klba     = (const float*)d_in[14];
    const float* Vlba     = (const float*)d_in[15];
    const float* l1w      = (const float*)d_in[16];
    const float* l1b      = (const float*)d_in[17];
    const float* l2w      = (const float*)d_in[18];
    const float* l2b      = (const float*)d_in[19];
    const float* gw       = (const float*)d_in[20];
    const float* gb       = (const float*)d_in[21];
    float* out = (float*)d_out;

    cudaFuncSetAttribute(fissa_kernel,
                         cudaFuncAttributeMaxDynamicSharedMemorySize, SMEM_BYTES);
    fissa_kernel<<<B_, TPB, SMEM_BYTES>>>(ui, pi, ni, pmask, item_emb, pos_emb,
                                          Qs, Ks, Vs, c1w, c1b, c2w, c2b, qitem,
                                          Klba, Vlba, l1w, l1b, l2w, l2b, gw, gb,
                                          out);
}

// round 14
// speedup vs baseline: 3.6561x; 3.6177x over previous
#include <cuda_runtime.h>
#include <math.h>

#define B_    1024
#define L_    50
#define D_    64
#define S_    2
#define LDX   68          // tile row stride (mult of 4 -> float4-aligned rows)
#define LDM   52          // scores / c-weight row stride (mult of 4)
#define TPB   256
#define NEGV  (-4294967295.0f)

// ---- shared memory layout (floats) ----
#define OFF_X    0                        // running x (starts as `inputs`, ends as loc)
#define OFF_T1   (OFF_X  + L_*LDX)        // temp tile 1
#define OFF_T2   (OFF_T1 + L_*LDX)        // temp tile 2
#define OFF_SC   (OFF_T2 + L_*LDX)        // 50x52 scores / c1 / c2 / epilogue scratch
#define OFF_PM   (OFF_SC + L_*LDM)        // padding mask (50)
#define OFF_G1   (OFF_PM + 64)            // ie . gw[0:64] per position
#define OFF_GLO  (OFF_G1 + 64)            // glo vector (64)
#define OFF_GW   (OFF_GLO + 64)           // gated_weight (192) + gglo scalar @192
#define SMEM_F   (OFF_GW + 200)
#define SMEM_BYTES (SMEM_F * 4)           // 52768 B -> 4 CTAs/SM

__device__ __forceinline__ float warp_sum(float v) {
#pragma unroll
    for (int o = 16; o; o >>= 1) v += __shfl_xor_sync(0xffffffffu, v, o);
    return v;
}
__device__ __forceinline__ float warp_max(float v) {
#pragma unroll
    for (int o = 16; o; o >>= 1) v = fmaxf(v, __shfl_xor_sync(0xffffffffu, v, o));
    return v;
}
__device__ __forceinline__ float sigmoidf_(float x) {
    return 1.0f / (1.0f + expf(-x));
}

// acc += s * vec (componentwise), all in registers
__device__ __forceinline__ void fma4(float4& acc, float s, const float4 vec) {
    acc.x = fmaf(s, vec.x, acc.x);
    acc.y = fmaf(s, vec.y, acc.y);
    acc.z = fmaf(s, vec.z, acc.z);
    acc.w = fmaf(s, vec.w, acc.w);
}

// scalar acc += dot(q, k)
__device__ __forceinline__ float dot4acc(float acc, float4 q, float4 k) {
    float t = fmaf(q.x, k.x, acc);
    t = fmaf(q.y, k.y, t);
    t = fmaf(q.z, k.z, t);
    return fmaf(q.w, k.w, t);
}

// LayerNorm over D=64 for each of L_ rows (warp per row), in place.
__device__ __forceinline__ void ln_rows(float* p) {
    const int lane = threadIdx.x & 31, wid = threadIdx.x >> 5;
    for (int l = wid; l < L_; l += 8) {
        float v0 = p[l*LDX + lane], v1 = p[l*LDX + lane + 32];
        float mean = warp_sum(v0 + v1) * (1.0f/64.0f);
        float d0 = v0 - mean, d1 = v1 - mean;
        float var = warp_sum(d0*d0 + d1*d1) * (1.0f/64.0f);
        float inv = rsqrtf(var + 1e-8f);
        p[l*LDX + lane]      = d0 * inv;
        p[l*LDX + lane + 32] = d1 * inv;
    }
}

// dst[l, d] = sum_k src[l, k] * W[k, d]
// src: L_ x LDX smem; W: 64x64 GLOBAL (L1/L2-resident, broadcast across warp).
// Main: group g owns rows {g, g+16, g+32}. Rows 48-49: cooperative scalar pass
// on threads 0-127 (one output each; trivial register footprint, no cloned loop).
__device__ __forceinline__ void mm_LW(float* __restrict__ dst,
                                      const float* __restrict__ src,
                                      const float* __restrict__ Wg) {
    const int tid = threadIdx.x;
    const int d4 = (tid & 15) * 4;
    const int g  = tid >> 4;
    const int rb0 = g*LDX, rb1 = (g+16)*LDX, rb2 = (g+32)*LDX;
    float4 a0 = make_float4(0.f,0.f,0.f,0.f), a1 = a0, a2 = a0;
#pragma unroll
    for (int k = 0; k < D_; k += 4) {
        const float4 x0 = *(const float4*)&src[rb0 + k];
        const float4 x1 = *(const float4*)&src[rb1 + k];
        const float4 x2 = *(const float4*)&src[rb2 + k];
#pragma unroll
        for (int kk = 0; kk < 4; ++kk) {
            const float4 wv4 = __ldg((const float4*)&Wg[(k + kk)*D_ + d4]);
            fma4(a0, ((const float*)&x0)[kk], wv4);
            fma4(a1, ((const float*)&x1)[kk], wv4);
            fma4(a2, ((const float*)&x2)[kk], wv4);
        }
    }
    *(float4*)&dst[rb0 + d4] = a0;
    *(float4*)&dst[rb1 + d4] = a1;
    *(float4*)&dst[rb2 + d4] = a2;
    // tail rows 48,49: tid<128 -> row = 48 + (tid>>6), col = tid&63
    if (tid < 128) {
        const int row = 48 + (tid >> 6);
        const int col = tid & 63;
        const float* srow = &src[row*LDX];
        float acc = 0.0f;
#pragma unroll 4
        for (int k = 0; k < D_; ++k)
            acc = fmaf(srow[k], __ldg(&Wg[k*D_ + col]), acc);
        dst[row*LDX + col] = acc;
    }
}

// apply score epilogue for one (q, kk) value
__device__ __forceinline__ float sc_fix(float v, int q, int kk, const float* pm) {
    v *= 0.125f;
    if (kk > q) v = NEGV;
    if (pm[kk] == 0.0f) v = NEGV;
    return v * pm[q];
}

// scores[q, k] = (Q[q,:] . K[k,:]) / 8, then tril/keymask NEG fill, then * pm[q]
// Main: q rows {g, g+16, g+32}; k cols kd + 16c (col 3 clamped, store-guarded).
// Tail: q rows 48,49 scalar on threads 0-127.
__device__ __forceinline__ void mm_scores(float* __restrict__ sc,
                                          const float* __restrict__ Q,
                                          const float* __restrict__ Kx,
                                          const float* __restrict__ pm) {
    const int tid = threadIdx.x;
    const int kd = tid & 15;
    const int g  = tid >> 4;
    const int q0 = g, q1 = g + 16, q2 = g + 32;
    const int k0 = kd, k1 = kd + 16, k2 = kd + 32, k3 = kd + 48;
    const int kb0 = k0*LDX, kb1 = k1*LDX, kb2 = k2*LDX;
    const int kb3 = (k3 < L_ ? k3 : L_ - 1) * LDX;
    float4 a0 = make_float4(0.f,0.f,0.f,0.f), a1 = a0, a2 = a0;
#pragma unroll
    for (int d = 0; d < D_; d += 4) {
        const float4 v0 = *(const float4*)&Q[q0*LDX + d];
        const float4 v1 = *(const float4*)&Q[q1*LDX + d];
        const float4 v2 = *(const float4*)&Q[q2*LDX + d];
        const float4 c0 = *(const float4*)&Kx[kb0 + d];
        const float4 c1 = *(const float4*)&Kx[kb1 + d];
        const float4 c2 = *(const float4*)&Kx[kb2 + d];
        const float4 c3 = *(const float4*)&Kx[kb3 + d];
        a0.x = dot4acc(a0.x, v0, c0); a0.y = dot4acc(a0.y, v0, c1);
        a0.z = dot4acc(a0.z, v0, c2); a0.w = dot4acc(a0.w, v0, c3);
        a1.x = dot4acc(a1.x, v1, c0); a1.y = dot4acc(a1.y, v1, c1);
        a1.z = dot4acc(a1.z, v1, c2); a1.w = dot4acc(a1.w, v1, c3);
        a2.x = dot4acc(a2.x, v2, c0); a2.y = dot4acc(a2.y, v2, c1);
        a2.z = dot4acc(a2.z, v2, c2); a2.w = dot4acc(a2.w, v2, c3);
    }
    sc[q0*LDM + k0] = sc_fix(a0.x, q0, k0, pm);
    sc[q0*LDM + k1] = sc_fix(a0.y, q0, k1, pm);
    sc[q0*LDM + k2] = sc_fix(a0.z, q0, k2, pm);
    sc[q1*LDM + k0] = sc_fix(a1.x, q1, k0, pm);
    sc[q1*LDM + k1] = sc_fix(a1.y, q1, k1, pm);
    sc[q1*LDM + k2] = sc_fix(a1.z, q1, k2, pm);
    sc[q2*LDM + k0] = sc_fix(a2.x, q2, k0, pm);
    sc[q2*LDM + k1] = sc_fix(a2.y, q2, k1, pm);
    sc[q2*LDM + k2] = sc_fix(a2.z, q2, k2, pm);
    if (k3 < L_) {
        sc[q0*LDM + k3] = sc_fix(a0.w, q0, k3, pm);
        sc[q1*LDM + k3] = sc_fix(a1.w, q1, k3, pm);
        sc[q2*LDM + k3] = sc_fix(a2.w, q2, k3, pm);
    }
    // tail q rows 48,49: tid<128 -> q = 48 + (tid>>6), k = tid&63 (k<50)
    if (tid < 128) {
        const int q = 48 + (tid >> 6);
        const int k = tid & 63;
        if (k < L_) {
            const float* qrow = &Q[q*LDX];
            const float* krow = &Kx[k*LDX];
            float acc = 0.0f;
#pragma unroll 4
            for (int d = 0; d < D_; ++d)
                acc = fmaf(qrow[d], krow[d], acc);
            sc[q*LDM + k] = sc_fix(acc, q, k, pm);
        }
    }
}

// epilogue helper (vector rows)
template<bool RELU>
__device__ __forceinline__ void sm_epi(float* __restrict__ dst,
                                       const float* __restrict__ res,
                                       const float* __restrict__ bias_g,
                                       const float* __restrict__ pm,
                                       float4 acc, int irow, int d4) {
    const float bias_ = bias_g ? bias_g[irow] : 0.0f;
    const float p_    = pm ? pm[irow] : 1.0f;
    float4 o_;
    if (res) {
        const float4 rv_ = *(const float4*)&res[irow*LDX + d4];
        o_.x = acc.x + bias_ + rv_.x;
        o_.y = acc.y + bias_ + rv_.y;
        o_.z = acc.z + bias_ + rv_.z;
        o_.w = acc.w + bias_ + rv_.w;
    } else {
        o_.x = acc.x + bias_; o_.y = acc.y + bias_;
        o_.z = acc.z + bias_; o_.w = acc.w + bias_;
    }
    if (RELU) {
        o_.x = fmaxf(o_.x, 0.0f); o_.y = fmaxf(o_.y, 0.0f);
        o_.z = fmaxf(o_.z, 0.0f); o_.w = fmaxf(o_.w, 0.0f);
    }
    o_.x *= p_; o_.y *= p_; o_.z *= p_; o_.w *= p_;
    *(float4*)&dst[irow*LDX + d4] = o_;
}

// dst[i, d] = sum_j M[i, j] * src[j, d]  (+bias[i]) (+res[i,d]) (relu) (*pm[i])
// M: 50 x LDM smem, src/res/dst: L_ x LDX smem.
// Main: i rows {g, g+16, g+32}. Tail: rows 48,49 scalar on threads 0-127.
template<bool RELU>
__device__ __forceinline__ void mm_SM(float* __restrict__ dst,
                                      const float* __restrict__ M,
                                      const float* __restrict__ src,
                                      const float* __restrict__ res,
                                      const float* __restrict__ bias_g,
                                      const float* __restrict__ pm) {
    const int tid = threadIdx.x;
    const int d4 = (tid & 15) * 4;
    const int g  = tid >> 4;
    const int i0 = g, i1 = g + 16, i2 = g + 32;
    float4 a0 = make_float4(0.f,0.f,0.f,0.f), a1 = a0, a2 = a0;
#pragma unroll
    for (int j = 0; j < 48; j += 4) {
        const float4 m0 = *(const float4*)&M[i0*LDM + j];
        const float4 m1 = *(const float4*)&M[i1*LDM + j];
        const float4 m2 = *(const float4*)&M[i2*LDM + j];
#pragma unroll
        for (int jj = 0; jj < 4; ++jj) {
            const float4 sv = *(const float4*)&src[(j + jj)*LDX + d4];
            fma4(a0, ((const float*)&m0)[jj], sv);
            fma4(a1, ((const float*)&m1)[jj], sv);
            fma4(a2, ((const float*)&m2)[jj], sv);
        }
    }
#pragma unroll
    for (int j = 48; j < L_; ++j) {
        const float4 sv = *(const float4*)&src[j*LDX + d4];
        fma4(a0, M[i0*LDM + j], sv);
        fma4(a1, M[i1*LDM + j], sv);
        fma4(a2, M[i2*LDM + j], sv);
    }
    sm_epi<RELU>(dst, res, bias_g, pm, a0, i0, d4);
    sm_epi<RELU>(dst, res, bias_g, pm, a1, i1, d4);
    sm_epi<RELU>(dst, res, bias_g, pm, a2, i2, d4);
    // tail rows 48,49: tid<128 -> i = 48 + (tid>>6), col = tid&63
    if (tid < 128) {
        const int i   = 48 + (tid >> 6);
        const int col = tid & 63;
        const float* mrow = &M[i*LDM];
        float acc = 0.0f;
#pragma unroll 5
        for (int j = 0; j < L_; ++j)
            acc = fmaf(mrow[j], src[j*LDX + col], acc);
        const float bias_ = bias_g ? bias_g[i] : 0.0f;
        const float p_    = pm ? pm[i] : 1.0f;
        float v = acc + bias_;
        if (res)  v += res[i*LDX + col];
        if (RELU) v = fmaxf(v, 0.0f);
        dst[i*LDX + col] = v * p_;
    }
}

// gather + positional embedding + mask into dst (L_ x LDX), no LN.
__device__ __forceinline__ void build_inputs(float* __restrict__ dst,
                                             const int* __restrict__ ui_row,
                                             const float* __restrict__ item_emb,
                                             const float* __restrict__ pos_emb,
                                             const float* __restrict__ pm) {
    const int tid = threadIdx.x;
    for (int idx = tid; idx < L_*16; idx += TPB) {
        const int l = idx >> 4, c4 = (idx & 15) * 4;
        const int it = __ldg(&ui_row[l]);
        const float4 e  = __ldg((const float4*)&item_emb[it*D_ + c4]);
        const float4 pe = __ldg((const float4*)&pos_emb[l*D_ + c4]);
        const float p = pm[l];
        *(float4*)&dst[l*LDX + c4] =
            make_float4((e.x+pe.x)*p, (e.y+pe.y)*p, (e.z+pe.z)*p, (e.w+pe.w)*p);
    }
}

__global__ void __launch_bounds__(TPB, 4)
fissa_kernel(const int* __restrict__ ui, const int* __restrict__ pi,
             const int* __restrict__ ni, const float* __restrict__ pmask,
             const float* __restrict__ item_emb, const float* __restrict__ pos_emb,
             const float* __restrict__ Qs, const float* __restrict__ Ks,
             const float* __restrict__ Vs,
             const float* __restrict__ c1w, const float* __restrict__ c1b,
             const float* __restrict__ c2w, const float* __restrict__ c2b,
             const float* __restrict__ qitem,
             const float* __restrict__ Klba, const float* __restrict__ Vlba,
             const float* __restrict__ l1w, const float* __restrict__ l1b,
             const float* __restrict__ l2w, const float* __restrict__ l2b,
             const float* __restrict__ gw, const float* __restrict__ gb,
             float* __restrict__ out) {
    extern __shared__ float sm[];
    float* s_x   = sm + OFF_X;
    float* t1    = sm + OFF_T1;
    float* t2    = sm + OFF_T2;
    float* s_sc  = sm + OFF_SC;
    float* s_pm  = sm + OFF_PM;
    float* s_g1  = sm + OFF_G1;
    float* s_glo = sm + OFF_GLO;
    float* s_gw  = sm + OFF_GW;

    const int b    = blockIdx.x;
    const int tid  = threadIdx.x;
    const int lane = tid & 31;
    const int wid  = tid >> 5;

    // ---- prologue ----
    if (tid < 192) s_gw[tid] = gw[tid];
    if (tid < L_)  s_pm[tid] = pmask[b*L_ + tid];
    __syncthreads();

    build_inputs(s_x, ui + b*L_, item_emb, pos_emb, s_pm);
    // g1[l] = ie[l] . gw[0:64]
    for (int l = wid; l < L_; l += 8) {
        const int it = __ldg(&ui[b*L_ + l]);
        float v = item_emb[it*D_ + lane] * s_gw[lane]
                + item_emb[it*D_ + lane + 32] * s_gw[lane + 32];
        v = warp_sum(v);
        if (lane == 0) s_g1[l] = v;
    }
    __syncthreads();
    ln_rows(s_x);                        // x = inputs = LN((ie + pos) * pm)
    __syncthreads();

    // ---- S self-attention blocks ----
    for (int s = 0; s < S_; ++s) {
        mm_LW(t1, s_x, Qs + s*D_*D_);            // Qx
        mm_LW(t2, s_x, Ks + s*D_*D_);            // Kx
        __syncthreads();
        mm_scores(s_sc, t1, t2, s_pm);
        __syncthreads();
        mm_LW(t1, s_x, Vs + s*D_*D_);            // Vx (Qx dead)
        __syncthreads();
        mm_SM<false>(t2, s_sc, t1, s_x, nullptr, nullptr);   // att = sc@Vx + x
        __syncthreads();
        // stage c1 (scores dead) + LN(att)
        for (int idx = tid; idx < L_*L_; idx += TPB) {
            const int i = idx / L_, j = idx - i*L_;
            s_sc[i*LDM + j] = __ldg(&c1w[s*L_*L_ + idx]);
        }
        ln_rows(t2);
        __syncthreads();
        mm_SM<true>(t1, s_sc, t2, nullptr, c1b + s*L_, nullptr);  // h
        __syncthreads();
        for (int idx = tid; idx < L_*L_; idx += TPB) {
            const int i = idx / L_, j = idx - i*L_;
            s_sc[i*LDM + j] = __ldg(&c2w[s*L_*L_ + idx]);
        }
        __syncthreads();
        mm_SM<false>(s_x, s_sc, t1, t2, c2b + s*L_, s_pm);   // ff -> x
        __syncthreads();
        ln_rows(s_x);
        __syncthreads();
    }
    // s_x = loc from here on (untouched below)

    // ---- LBA global attention (tile-free formulation) ----
    build_inputs(t1, ui + b*L_, item_emb, pos_emb, s_pm);
    __syncthreads();
    ln_rows(t1);
    __syncthreads();

    float* kq = s_sc;          // 64
    float* lg = s_sc + 64;     // 50 logits -> softmax probs
    float* wv = s_sc + 128;    // 64 column sums

    // kq[e] = Klba[e,:] . q
    for (int e = wid; e < D_; e += 8) {
        float v = __ldg(&Klba[e*D_ + lane]) * __ldg(&qitem[lane])
                + __ldg(&Klba[e*D_ + lane + 32]) * __ldg(&qitem[lane + 32]);
        v = warp_sum(v);
        if (lane == 0) kq[e] = v;
    }
    __syncthreads();
    // lg[l] = inputs[l] . kq  (+ key mask)
    for (int l = wid; l < L_; l += 8) {
        float v = t1[l*LDX + lane] * kq[lane]
                + t1[l*LDX + lane + 32] * kq[lane + 32];
        v = warp_sum(v);
        if (lane == 0) lg[l] = (s_pm[l] == 0.0f) ? NEGV : v;
    }
    __syncthreads();
    // softmax over 50 (warp 0)
    if (wid == 0) {
        float v0 = (lane < L_) ? lg[lane] : -3.0e38f;
        float v1 = (lane + 32 < L_) ? lg[lane + 32] : -3.0e38f;
        float m = warp_max(fmaxf(v0, v1));
        float e0 = (lane < L_) ? expf(v0 - m) : 0.0f;
        float e1 = (lane + 32 < L_) ? expf(v1 - m) : 0.0f;
        float ssum = warp_sum(e0 + e1);
        if (lane < L_)      lg[lane]      = e0 / ssum;
        if (lane + 32 < L_) lg[lane + 32] = e1 / ssum;
    }
    __syncthreads();
    // wv[e] = sum_l p[l] * inputs[l, e]
    if (tid < D_) {
        float a = 0.0f;
        for (int l = 0; l < L_; ++l) a = fmaf(lg[l], t1[l*LDX + tid], a);
        wv[tid] = a;
    }
    __syncthreads();
    // glo[d] = sum_e wv[e] * Vlba[e, d]
    if (tid < D_) {
        float a = 0.0f;
        for (int e = 0; e < D_; ++e) a = fmaf(wv[e], __ldg(&Vlba[e*D_ + tid]), a);
        s_glo[tid] = a;
    }
    __syncthreads();
    // LN -> l1/l2 residual -> LN -> gglo scalar (warp 0)
    if (wid == 0) {
        float v0 = s_glo[lane], v1 = s_glo[lane + 32];
        float mean = warp_sum(v0 + v1) * (1.0f/64.0f);
        float d0 = v0 - mean, d1 = v1 - mean;
        float var = warp_sum(d0*d0 + d1*d1) * (1.0f/64.0f);
        float inv = rsqrtf(var + 1e-8f);
        float g0 = d0 * inv, g1v = d1 * inv;
        const float w1 = l1w[0], bb1 = l1b[0], w2 = l2w[0], bb2 = l2b[0];
        float h0 = fmaxf(w1*g0 + bb1, 0.0f);
        float h1 = fmaxf(w1*g1v + bb1, 0.0f);
        g0  = w2*h0 + bb2 + g0;
        g1v = w2*h1 + bb2 + g1v;
        mean = warp_sum(g0 + g1v) * (1.0f/64.0f);
        d0 = g0 - mean; d1 = g1v - mean;
        var = warp_sum(d0*d0 + d1*d1) * (1.0f/64.0f);
        inv = rsqrtf(var + 1e-8f);
        g0 = d0 * inv; g1v = d1 * inv;
        s_glo[lane] = g0; s_glo[lane + 32] = g1v;
        float gg = warp_sum(g0 * s_gw[64 + lane] + g1v * s_gw[96 + lane]);
        if (lane == 0) s_gw[192] = gg;   // glo . gw[64:128]
    }
    __syncthreads();

    // ---- gated fusion + final LN + pos/neg dots ----
    const float gbias = gb[0];
    for (int t = wid; t < 2*L_; t += 8) {
        const int pn = (t >= L_);
        const int l  = t - pn*L_;
        const int*  items = pn ? ni : pi;
        const int   it = __ldg(&items[b*L_ + l]);
        const float e0 = item_emb[it*D_ + lane];
        const float e1 = item_emb[it*D_ + lane + 32];
        const float dot3 = warp_sum(e0 * s_gw[128 + lane] + e1 * s_gw[160 + lane]);
        const float logit = s_g1[l] + s_gw[192] + dot3 + gbias;
        const float g = sigmoidf_(sigmoidf_(logit));
        float o0 = (s_x[l*LDX + lane]      * g + s_glo[lane]      * (1.0f - g)) * s_pm[l];
        float o1 = (s_x[l*LDX + lane + 32] * g + s_glo[lane + 32] * (1.0f - g)) * s_pm[l];
        const float mean = warp_sum(o0 + o1) * (1.0f/64.0f);
        const float d0 = o0 - mean, d1 = o1 - mean;
        const float var = warp_sum(d0*d0 + d1*d1) * (1.0f/64.0f);
        const float inv = rsqrtf(var + 1e-8f);
        const float r = warp_sum(d0*inv*e0 + d1*inv*e1);
        if (lane == 0) out[pn*B_*L_ + b*L_ + l] = r;
    }
}

extern "C" void kernel_launch(void* const* d_in, const int* in_sizes, int n_in,
                              void* d_out, int out_size) {
    const int*   ui       = (const int*)  d_in[0];
    const int*   pi       = (const int*)  d_in[1];
    const int*   ni       = (const int*)  d_in[2];
    const float* pmask    = (const float*)d_in[3];
    const float* item_emb = (const float*)d_in[4];
    const float* pos_emb  = (const float*)d_in[5];
    const float* Qs       = (const float*)d_in[6];
    const float* Ks       = (const float*)d_in[7];
    const float* Vs       = (const float*)d_in[8];
    const float* c1w      = (const float*)d_in[9];
    const float* c1b      = (const float*)d_in[10];
    const float* c2w      = (const float*)d_in[11];
    const float* c2b      = (const float*)d_in[12];
    const float* qitem    = (const float*)d_in[13];
    const float* Klba     = (const float*)d_in[14];
    const float* Vlba     = (const float*)d_in[15];
    const float* l1w      = (const float*)d_in[16];
    const float* l1b      = (const float*)d_in[17];
    const float* l2w      = (const float*)d_in[18];
    const float* l2b      = (const float*)d_in[19];
    const float* gw       = (const float*)d_in[20];
    const float* gb       = (const float*)d_in[21];
    float* out = (float*)d_out;

    cudaFuncSetAttribute(fissa_kernel,
                         cudaFuncAttributeMaxDynamicSharedMemorySize, SMEM_BYTES);
    fissa_kernel<<<B_, TPB, SMEM_BYTES>>>(ui, pi, ni, pmask, item_emb, pos_emb,
                                          Qs, Ks, Vs, c1w, c1b, c2w, c2b, qitem,
                                          Klba, Vlba, l1w, l1b, l2w, l2b, gw, gb,
                                          out);
}